// round 17
// baseline (speedup 1.0000x reference)
#include <cuda_runtime.h>
#include <cuda_bf16.h>
#include <math.h>
#include <stdint.h>

#define LTOK 65536
#define CDIM 192
#define HIDD 768

typedef unsigned long long ull;
typedef unsigned int u32;

// ---------------- scratch (static device globals; no allocation) ----------------
__device__ __nv_bfloat16 g_xwb[LTOK * CDIM];   // LN1 out (window order) / LN2 out (token order)
__device__ __nv_bfloat16 g_q[LTOK * CDIM];     // [win,head,n,d] bf16 (q pre-scaled)
__device__ __nv_bfloat16 g_k[LTOK * CDIM];
__device__ __nv_bfloat16 g_v[LTOK * CDIM];
__device__ __nv_bfloat16 g_aob[LTOK * CDIM];   // attention out, window order, bf16
__device__ float g_xr[LTOK * CDIM];            // first residual, token order, fp32
__device__ __nv_bfloat16 g_hb[LTOK * HIDD];    // MLP hidden, bf16
__device__ __nv_bfloat16 g_bias6b[6 * 256 * 256];   // rel-pos bias, bf16
// transposed bf16 weights: [N, K] row-major
__device__ __nv_bfloat16 g_wqkv[576 * 192];
__device__ __nv_bfloat16 g_wproj[192 * 192];
__device__ __nv_bfloat16 g_wfc1[768 * 192];
__device__ __nv_bfloat16 g_wfc2[192 * 768];

// ---------------- mma.sync / cp.async helpers ----------------
__device__ __forceinline__ u32 smem_u32(const void* p) {
    u32 a;
    asm("{ .reg .u64 t; cvta.to.shared.u64 t, %1; cvt.u32.u64 %0, t; }" : "=r"(a) : "l"(p));
    return a;
}
#define LDM4(R, addr)                                                            \
    asm volatile("ldmatrix.sync.aligned.m8n8.x4.shared.b16 {%0,%1,%2,%3}, [%4];" \
        : "=r"((R)[0]), "=r"((R)[1]), "=r"((R)[2]), "=r"((R)[3]) : "r"(addr))

#define LDM4T(R, addr)                                                           \
    asm volatile("ldmatrix.sync.aligned.m8n8.x4.trans.shared.b16 {%0,%1,%2,%3}, [%4];" \
        : "=r"((R)[0]), "=r"((R)[1]), "=r"((R)[2]), "=r"((R)[3]) : "r"(addr))

#define MMA(dd, A, B0, B1)                                                       \
    asm volatile("mma.sync.aligned.m16n8k16.row.col.f32.bf16.bf16.f32 "          \
        "{%0,%1,%2,%3}, {%4,%5,%6,%7}, {%8,%9}, {%0,%1,%2,%3};"                  \
        : "+f"((dd)[0]), "+f"((dd)[1]), "+f"((dd)[2]), "+f"((dd)[3])             \
        : "r"((A)[0]), "r"((A)[1]), "r"((A)[2]), "r"((A)[3]), "r"(B0), "r"(B1))

__device__ __forceinline__ void cpasync16(u32 dst, const void* src) {
    asm volatile("cp.async.cg.shared.global [%0], [%1], 16;" :: "r"(dst), "l"(src) : "memory");
}
#define CP_COMMIT() asm volatile("cp.async.commit_group;" ::: "memory")
#define CP_WAIT1()  asm volatile("cp.async.wait_group 1;" ::: "memory")

__device__ __forceinline__ u32 bfpack(float a, float b) {
    __nv_bfloat162 h = __floats2bfloat162_rn(a, b);
    return *(u32*)&h;
}

__device__ __forceinline__ float gelu_exact(float x) {
    return 0.5f * x * (1.0f + erff(x * 0.70710678118654752f));
}

// ============ fused prep: weight transpose + bias gather + LN1 (independent) ============
// blocks [0,432): transw ; [432,1968): bias6 ; [1968,2560): LN1 (shift+partition)
__global__ __launch_bounds__(256) void prep_kernel(const float* __restrict__ qkvw,
                                                   const float* __restrict__ projw,
                                                   const float* __restrict__ fc1w,
                                                   const float* __restrict__ fc2w,
                                                   const int* __restrict__ rpi,
                                                   const float* __restrict__ rpb,
                                                   const float* __restrict__ x,
                                                   const float* __restrict__ n1g,
                                                   const float* __restrict__ n1b) {
    __shared__ float t[32][33];
    int b = blockIdx.x;
    int tid = threadIdx.x;
    if (b < 432) {
        const float* W; __nv_bfloat16* Wt; int K, N, tb;
        if (b < 108)      { W = qkvw;  Wt = g_wqkv;  K = 192; N = 576; tb = b; }
        else if (b < 144) { W = projw; Wt = g_wproj; K = 192; N = 192; tb = b - 108; }
        else if (b < 288) { W = fc1w;  Wt = g_wfc1;  K = 192; N = 768; tb = b - 144; }
        else              { W = fc2w;  Wt = g_wfc2;  K = 768; N = 192; tb = b - 288; }
        int ntiles = N >> 5;
        int tr = tb / ntiles, tc = tb - tr * ntiles;
        int tx = tid & 31, ty = tid >> 5;
#pragma unroll
        for (int rr = 0; rr < 4; rr++) {
            int k = tr * 32 + ty + rr * 8;
            t[ty + rr * 8][tx] = W[(size_t)k * N + tc * 32 + tx];
        }
        __syncthreads();
#pragma unroll
        for (int rr = 0; rr < 4; rr++) {
            int n = tc * 32 + ty + rr * 8;
            Wt[(size_t)n * K + tr * 32 + tx] = __float2bfloat16_rn(t[tx][ty + rr * 8]);
        }
    } else if (b < 1968) {
        int id = (b - 432) * 256 + tid;
        int head = id >> 16;
        int nm = id & 65535;
        g_bias6b[id] = __float2bfloat16_rn(rpb[rpi[nm] * 6 + head]);
    } else {
        int gwid = ((b - 1968) * 256 + tid) >> 5;
        int l = tid & 31;
        const int nwarp = 592 * 8;
        float gg[6], bb[6];
#pragma unroll
        for (int j = 0; j < 6; j++) { gg[j] = n1g[l + 32 * j]; bb[j] = n1b[l + 32 * j]; }
        for (int s = gwid; s < LTOK; s += nwarp) {
            const float* in = x + (size_t)s * CDIM;
            float v[6], sum = 0.0f, sq = 0.0f;
#pragma unroll
            for (int j = 0; j < 6; j++) {
                v[j] = in[l + 32 * j];
                sum += v[j];
                sq += v[j] * v[j];
            }
#pragma unroll
            for (int o = 16; o; o >>= 1) {
                sum += __shfl_xor_sync(0xffffffffu, sum, o);
                sq  += __shfl_xor_sync(0xffffffffu, sq, o);
            }
            float mean = sum * (1.0f / CDIM);
            float var = sq * (1.0f / CDIM) - mean * mean;
            float rs = rsqrtf(var + 1e-5f);
            int h = s >> 8, w = s & 255;
            int i = (h + 248) & 255, j2 = (w + 248) & 255;
            int r = (((i >> 4) << 4) + (j2 >> 4)) * 256 + ((i & 15) << 4) + (j2 & 15);
            __nv_bfloat16* dst = g_xwb + (size_t)r * CDIM;
#pragma unroll
            for (int j = 0; j < 6; j++)
                dst[l + 32 * j] = __float2bfloat16_rn((v[j] - mean) * rs * gg[j] + bb[j]);
        }
    }
}

// ============ LayerNorm (LN2): warp-per-token, bf16 out ============
__global__ __launch_bounds__(256) void ln_kernel(const float* __restrict__ gw,
                                                 const float* __restrict__ bw) {
    int gwid = (blockIdx.x * 256 + threadIdx.x) >> 5;
    int l = threadIdx.x & 31;
    int nwarp = (gridDim.x * 256) >> 5;

    float gg[6], bb[6];
#pragma unroll
    for (int j = 0; j < 6; j++) { gg[j] = gw[l + 32 * j]; bb[j] = bw[l + 32 * j]; }

    for (int s = gwid; s < LTOK; s += nwarp) {
        const float* in = g_xr + (size_t)s * CDIM;
        float v[6], sum = 0.0f, sq = 0.0f;
#pragma unroll
        for (int j = 0; j < 6; j++) {
            v[j] = in[l + 32 * j];
            sum += v[j];
            sq += v[j] * v[j];
        }
#pragma unroll
        for (int o = 16; o; o >>= 1) {
            sum += __shfl_xor_sync(0xffffffffu, sum, o);
            sq  += __shfl_xor_sync(0xffffffffu, sq, o);
        }
        float mean = sum * (1.0f / CDIM);
        float var = sq * (1.0f / CDIM) - mean * mean;
        float rs = rsqrtf(var + 1e-5f);
        __nv_bfloat16* dst = g_xwb + (size_t)s * CDIM;
#pragma unroll
        for (int j = 0; j < 6; j++)
            dst[l + 32 * j] = __float2bfloat16_rn((v[j] - mean) * rs * gg[j] + bb[j]);
    }
}

// ============ epilogue pair-store ============
template <int MODE>
__device__ __forceinline__ void store2(int r, int n, float2 v,
                                       const float* __restrict__ aux,
                                       float* __restrict__ outp) {
    if (MODE == 0) {
        int which = n / 192;
        int rem = n - which * 192;
        int head = rem >> 5, dd = rem & 31;
        int wnd = r >> 8, nn = r & 255;
        __nv_bfloat16* dst = ((which == 0) ? g_q : (which == 1) ? g_k : g_v)
                             + (size_t)((wnd * 6 + head) * 256 + nn) * 32 + dd;
        if (which == 0) {
            v.x *= 0.17677669529663687f;
            v.y *= 0.17677669529663687f;
        }
        *(u32*)dst = bfpack(v.x, v.y);
    } else if (MODE == 1) {
        int wnd = r >> 8, nn = r & 255;
        int i_ = ((wnd >> 4) << 4) + (nn >> 4);
        int j_ = ((wnd & 15) << 4) + (nn & 15);
        int s = (((i_ + 8) & 255) << 8) + ((j_ + 8) & 255);
        float2 a = *(const float2*)(aux + (size_t)s * CDIM + n);
        v.x += a.x; v.y += a.y;
        *(float2*)(g_xr + (size_t)s * CDIM + n) = v;
    } else if (MODE == 2) {
        *(u32*)(g_hb + (size_t)r * HIDD + n) = bfpack(gelu_exact(v.x), gelu_exact(v.y));
    } else {
        float2 a = *(const float2*)(g_xr + (size_t)r * CDIM + n);
        v.x += a.x; v.y += a.y;
        *(float2*)(outp + (size_t)r * CDIM + n) = v;
    }
}

// ============ A-resident GEMM, K=192: 128 threads, warp = 32m x 64n ============
// Crossbar-bound fix: per k-step 6 LDM4 feed 16 MMAs (was 4/8). B staged via
// cp.async (no register round-trip, no STS). 2 CTAs/SM (smem 102400 x2).
#define ARES_SMEM (128 * 400 + 2 * 64 * 400)
template <int MODE>
__global__ __launch_bounds__(128, 2) void tmmaA(const float* __restrict__ bias,
                                                const float* __restrict__ aux,
                                                float* __restrict__ outp, int NT) {
    extern __shared__ __align__(16) char sm[];
    char* As = sm;                       // 128 * 400
    u32 sa = smem_u32(As);
    u32 sb0 = sa + 51200;                // 2 buffers * 64 * 400

    const __nv_bfloat16* Ag = (MODE == 1) ? g_aob : g_xwb;
    const __nv_bfloat16* Wt = (MODE == 0) ? g_wqkv : (MODE == 1) ? g_wproj : g_wfc1;

    int tid = threadIdx.x;
    int wid = tid >> 5, l = tid & 31;
    int m0 = blockIdx.x * 128;

    // async B tile 0 -> buf0
#pragma unroll
    for (int j = 0; j < 12; j++) {
        int id = tid + j * 128;
        int row = id / 24, ch = id - row * 24;
        cpasync16(sb0 + row * 400 + ch * 16, Wt + (size_t)row * 192 + ch * 8);
    }
    CP_COMMIT();
    // async B tile 1 -> buf1
    if (NT > 1) {
        const __nv_bfloat16* W1 = Wt + (size_t)64 * 192;
#pragma unroll
        for (int j = 0; j < 12; j++) {
            int id = tid + j * 128;
            int row = id / 24, ch = id - row * 24;
            cpasync16(sb0 + 25600 + row * 400 + ch * 16, W1 + (size_t)row * 192 + ch * 8);
        }
    }
    CP_COMMIT();
    // A tile (plain LDG+STS, once)
#pragma unroll
    for (int j = 0; j < 24; j++) {
        int id = tid + j * 128;
        int row = id / 24, ch = id - row * 24;
        *(uint4*)(As + row * 400 + ch * 16) =
            *(const uint4*)(Ag + (size_t)(m0 + row) * 192 + ch * 8);
    }
    CP_WAIT1();          // B0 complete
    __syncthreads();

    u32 aBase0 = sa + (wid * 32 + (l & 15)) * 400 + (l >> 4) * 16;   // mt=0
    u32 aBase1 = aBase0 + 16 * 400;                                  // mt=1
    u32 bo = ((l & 7) + ((l >> 3) & 1) * 8) * 400 + (l >> 4) * 16;   // + jj*16*400
    int lq = l >> 2, lr = l & 3;

    for (int nt = 0; nt < NT; nt++) {
        int cur = nt & 1;
        u32 bBase = sb0 + cur * 25600 + bo;

        float d[2][8][4];
#pragma unroll
        for (int mt = 0; mt < 2; mt++)
#pragma unroll
            for (int nj = 0; nj < 8; nj++)
#pragma unroll
                for (int q = 0; q < 4; q++) d[mt][nj][q] = 0.0f;

#pragma unroll
        for (int ks = 0; ks < 12; ks++) {
            u32 a0[4], a1[4], r0[4], r1[4], r2[4], r3[4];
            LDM4(a0, aBase0 + ks * 32);
            LDM4(a1, aBase1 + ks * 32);
            LDM4(r0, bBase + ks * 32);
            LDM4(r1, bBase + 6400 + ks * 32);
            LDM4(r2, bBase + 12800 + ks * 32);
            LDM4(r3, bBase + 19200 + ks * 32);
            MMA(d[0][0], a0, r0[0], r0[2]);
            MMA(d[0][1], a0, r0[1], r0[3]);
            MMA(d[0][2], a0, r1[0], r1[2]);
            MMA(d[0][3], a0, r1[1], r1[3]);
            MMA(d[0][4], a0, r2[0], r2[2]);
            MMA(d[0][5], a0, r2[1], r2[3]);
            MMA(d[0][6], a0, r3[0], r3[2]);
            MMA(d[0][7], a0, r3[1], r3[3]);
            MMA(d[1][0], a1, r0[0], r0[2]);
            MMA(d[1][1], a1, r0[1], r0[3]);
            MMA(d[1][2], a1, r1[0], r1[2]);
            MMA(d[1][3], a1, r1[1], r1[3]);
            MMA(d[1][4], a1, r2[0], r2[2]);
            MMA(d[1][5], a1, r2[1], r2[3]);
            MMA(d[1][6], a1, r3[0], r3[2]);
            MMA(d[1][7], a1, r3[1], r3[3]);
        }

        // epilogue
#pragma unroll
        for (int mt = 0; mt < 2; mt++) {
            int ra = m0 + wid * 32 + mt * 16 + lq;
            int rb = ra + 8;
#pragma unroll
            for (int nj = 0; nj < 8; nj++) {
                int ng = nt * 64 + nj * 8 + lr * 2;
                float2 b2 = *(const float2*)(bias + ng);
                float2 v0 = make_float2(d[mt][nj][0] + b2.x, d[mt][nj][1] + b2.y);
                float2 v1 = make_float2(d[mt][nj][2] + b2.x, d[mt][nj][3] + b2.y);
                store2<MODE>(ra, ng, v0, aux, outp);
                store2<MODE>(rb, ng, v1, aux, outp);
            }
        }
        __syncthreads();                 // all warps done reading buf cur
        if (nt + 2 < NT) {
            const __nv_bfloat16* Wn = Wt + (size_t)(nt + 2) * 64 * 192;
#pragma unroll
            for (int j = 0; j < 12; j++) {
                int id = tid + j * 128;
                int row = id / 24, ch = id - row * 24;
                cpasync16(sb0 + cur * 25600 + row * 400 + ch * 16,
                          Wn + (size_t)row * 192 + ch * 8);
            }
        }
        CP_COMMIT();                     // one group per iteration (possibly empty)
        if (nt + 1 < NT) {
            CP_WAIT1();                  // B(nt+1) complete
            __syncthreads();
        }
    }
}

// ============ fc2 GEMM: K=768, BM=128, BN=192 single pass, double-buffered ============
// layout: A0@0 (10240), B0@10240 (15360), A1@25600, B1@35840 ; total 51200
#define FC2_SMEM (2 * (128 * 80 + 192 * 80))
__global__ __launch_bounds__(256) void tmmaF(const float* __restrict__ bias,
                                             float* __restrict__ outp) {
    extern __shared__ __align__(16) char smF[];
    int tid = threadIdx.x;
    int w = tid >> 5, l = tid & 31;
    int wm = w & 3, wn = w >> 2;   // 4 x 2 warps; warp tile 32 x 96
    int m0 = blockIdx.x * 128;

    const __nv_bfloat16* Ag = g_hb;
    const __nv_bfloat16* Wt = g_wfc2;

    u32 s0 = smem_u32(smF);
    u32 aOff = (wm * 32 + (l & 7) + ((l >> 3) & 1) * 8) * 80 + (l >> 4) * 16;
    u32 bOff = 10240 + (wn * 96 + (l & 7) + ((l >> 3) & 1) * 8) * 80 + (l >> 4) * 16;

    float d[2][12][4];
#pragma unroll
    for (int mt = 0; mt < 2; mt++)
#pragma unroll
        for (int nj = 0; nj < 12; nj++)
#pragma unroll
            for (int q = 0; q < 4; q++) d[mt][nj][q] = 0.0f;

    uint4 pa[2], pb[3];
#pragma unroll
    for (int j = 0; j < 2; j++) {
        int id = tid + j * 256;
        pa[j] = *(const uint4*)(Ag + (size_t)(m0 + (id >> 2)) * HIDD + (id & 3) * 8);
    }
#pragma unroll
    for (int j = 0; j < 3; j++) {
        int id = tid + j * 256;
        pb[j] = *(const uint4*)(Wt + (size_t)(id >> 2) * HIDD + (id & 3) * 8);
    }
#pragma unroll
    for (int j = 0; j < 2; j++) {
        int id = tid + j * 256;
        *(uint4*)(smF + (id >> 2) * 80 + (id & 3) * 16) = pa[j];
    }
#pragma unroll
    for (int j = 0; j < 3; j++) {
        int id = tid + j * 256;
        *(uint4*)(smF + 10240 + (id >> 2) * 80 + (id & 3) * 16) = pb[j];
    }
    __syncthreads();
    {
#pragma unroll
        for (int j = 0; j < 2; j++) {
            int id = tid + j * 256;
            pa[j] = *(const uint4*)(Ag + (size_t)(m0 + (id >> 2)) * HIDD + 32 + (id & 3) * 8);
        }
#pragma unroll
        for (int j = 0; j < 3; j++) {
            int id = tid + j * 256;
            pb[j] = *(const uint4*)(Wt + (size_t)(id >> 2) * HIDD + 32 + (id & 3) * 8);
        }
    }

    for (int kt = 0; kt < 24; kt++) {
        int cur = kt & 1;
        if (kt + 1 < 24) {
            char* base = smF + (1 - cur) * 25600;
#pragma unroll
            for (int j = 0; j < 2; j++) {
                int id = tid + j * 256;
                *(uint4*)(base + (id >> 2) * 80 + (id & 3) * 16) = pa[j];
            }
#pragma unroll
            for (int j = 0; j < 3; j++) {
                int id = tid + j * 256;
                *(uint4*)(base + 10240 + (id >> 2) * 80 + (id & 3) * 16) = pb[j];
            }
        }
        if (kt + 2 < 24) {
            int kc = (kt + 2) * 32;
#pragma unroll
            for (int j = 0; j < 2; j++) {
                int id = tid + j * 256;
                pa[j] = *(const uint4*)(Ag + (size_t)(m0 + (id >> 2)) * HIDD + kc + (id & 3) * 8);
            }
#pragma unroll
            for (int j = 0; j < 3; j++) {
                int id = tid + j * 256;
                pb[j] = *(const uint4*)(Wt + (size_t)(id >> 2) * HIDD + kc + (id & 3) * 8);
            }
        }
        u32 aBase = s0 + cur * 25600 + aOff;
        u32 bBase = s0 + cur * 25600 + bOff;
#pragma unroll
        for (int ks = 0; ks < 2; ks++) {
            u32 a0[4], a1[4];
            LDM4(a0, aBase + ks * 32);
            LDM4(a1, aBase + 1280 + ks * 32);
#pragma unroll
            for (int g = 0; g < 6; g++) {
                u32 rg[4];
                LDM4(rg, bBase + g * 1280 + ks * 32);
                MMA(d[0][2 * g],     a0, rg[0], rg[2]);
                MMA(d[0][2 * g + 1], a0, rg[1], rg[3]);
                MMA(d[1][2 * g],     a1, rg[0], rg[2]);
                MMA(d[1][2 * g + 1], a1, rg[1], rg[3]);
            }
        }
        __syncthreads();
    }

    int lq = l >> 2, lr = l & 3;
#pragma unroll
    for (int mt = 0; mt < 2; mt++) {
        int ra = m0 + wm * 32 + mt * 16 + lq;
        int rb = ra + 8;
#pragma unroll
        for (int nj = 0; nj < 12; nj++) {
            int ng = wn * 96 + nj * 8 + lr * 2;
            float2 b2 = *(const float2*)(bias + ng);
            float2 v0 = make_float2(d[mt][nj][0] + b2.x, d[mt][nj][1] + b2.y);
            float2 v1 = make_float2(d[mt][nj][2] + b2.x, d[mt][nj][3] + b2.y);
            store2<3>(ra, ng, v0, nullptr, outp);
            store2<3>(rb, ng, v1, nullptr, outp);
        }
    }
}

// ============ tensor-core attention: one block per (window, head) ============
#define ATT_SMEM (256 * 80 * 3)
__global__ __launch_bounds__(256, 2) void attn_mma(const float* __restrict__ mask) {
    extern __shared__ __align__(16) char sm[];
    char* Qs = sm;
    char* Ksm = sm + 256 * 80;
    char* Vsm = sm + 2 * 256 * 80;

    int bid = blockIdx.x;
    int wnd = bid / 6;
    int head = bid - wnd * 6;
    int tid = threadIdx.x;

    size_t gbase = (size_t)((wnd * 6 + head) * 256) * 32;
    const uint4* Qg = (const uint4*)(g_q + gbase);
    const uint4* Kg = (const uint4*)(g_k + gbase);
    const uint4* Vg = (const uint4*)(g_v + gbase);
    for (int i = tid; i < 1024; i += 256) {
        int row = i >> 2, c4 = i & 3;
        int off = row * 80 + c4 * 16;
        *(uint4*)(Qs + off)  = Qg[i];
        *(uint4*)(Ksm + off) = Kg[i];
        *(uint4*)(Vsm + off) = Vg[i];
    }
    __syncthreads();

    int w = tid >> 5, l = tid & 31;
    u32 sQ = smem_u32(Qs), sK = smem_u32(Ksm), sV = smem_u32(Vsm);
    bool border = ((wnd >> 4) == 15) || ((wnd & 15) == 15);

#pragma unroll 1
    for (int hh = 0; hh < 2; hh++) {
        int qr = hh * 128 + w * 16;
        u32 qa[8];
        LDM4(qa,     sQ + (qr + (l & 15)) * 80 + (l >> 4) * 16);
        LDM4(qa + 4, sQ + (qr + (l & 15)) * 80 + 32 + (l >> 4) * 16);

        int r0 = qr + (l >> 2);
        const __nv_bfloat16* bA = g_bias6b + head * 65536 + r0 * 256;
        const __nv_bfloat16* bB = bA + 2048;
        const float* mA = mask + (size_t)wnd * 65536 + r0 * 256;
        const float* mB = mA + 2048;

        float sA = 0.0f, sB = 0.0f;
        float o[4][4];
#pragma unroll
        for (int nt = 0; nt < 4; nt++)
#pragma unroll
            for (int q = 0; q < 4; q++) o[nt][q] = 0.0f;

#pragma unroll 1
        for (int kh = 0; kh < 2; kh++) {
            int kb0 = kh * 128;
            float d[16][4];
#pragma unroll
            for (int t = 0; t < 16; t++)
#pragma unroll
                for (int q = 0; q < 4; q++) d[t][q] = 0.0f;

#pragma unroll
            for (int t = 0; t < 16; t++) {
                u32 kb[4];
                LDM4(kb, sK + (kb0 + t * 8 + (l & 7)) * 80 + (l >> 3) * 16);
                MMA(d[t], qa, kb[0], kb[1]);
                MMA(d[t], qa + 4, kb[2], kb[3]);
            }

            u32 pbf[8][4];
#pragma unroll
            for (int t = 0; t < 16; t++) {
                int c = kb0 + t * 8 + 2 * (l & 3);
                float2 aA = __bfloat1622float2(*(const __nv_bfloat162*)(bA + c));
                float2 aB = __bfloat1622float2(*(const __nv_bfloat162*)(bB + c));
                if (border) {
                    float2 ma = *(const float2*)(mA + c);
                    float2 mb = *(const float2*)(mB + c);
                    aA.x += ma.x; aA.y += ma.y;
                    aB.x += mb.x; aB.y += mb.y;
                }
                float p0 = __expf(d[t][0] + aA.x);
                float p1 = __expf(d[t][1] + aA.y);
                float p2 = __expf(d[t][2] + aB.x);
                float p3 = __expf(d[t][3] + aB.y);
                sA += p0 + p1;
                sB += p2 + p3;
                int kt = t >> 1, s4 = (t & 1) * 2;
                pbf[kt][s4]     = bfpack(p0, p1);
                pbf[kt][s4 + 1] = bfpack(p2, p3);
            }

#pragma unroll
            for (int kt = 0; kt < 8; kt++) {
                u32 v0[4], v1[4];
                u32 vaddr = sV + (kb0 + kt * 16 + (l & 7) + ((l >> 3) & 1) * 8) * 80 + (l >> 4) * 16;
                LDM4T(v0, vaddr);
                LDM4T(v1, vaddr + 32);
                MMA(o[0], pbf[kt], v0[0], v0[1]);
                MMA(o[1], pbf[kt], v0[2], v0[3]);
                MMA(o[2], pbf[kt], v1[0], v1[1]);
                MMA(o[3], pbf[kt], v1[2], v1[3]);
            }
        }

        sA += __shfl_xor_sync(0xffffffffu, sA, 1);
        sA += __shfl_xor_sync(0xffffffffu, sA, 2);
        sB += __shfl_xor_sync(0xffffffffu, sB, 1);
        sB += __shfl_xor_sync(0xffffffffu, sB, 2);
        float invA = 1.0f / sA, invB = 1.0f / sB;

        __nv_bfloat16* OA = g_aob + (size_t)(wnd * 256 + r0) * CDIM + head * 32;
        __nv_bfloat16* OB = OA + (size_t)8 * CDIM;
#pragma unroll
        for (int nt = 0; nt < 4; nt++) {
            int c = nt * 8 + 2 * (l & 3);
            *(u32*)(OA + c) = bfpack(o[nt][0] * invA, o[nt][1] * invA);
            *(u32*)(OB + c) = bfpack(o[nt][2] * invB, o[nt][3] * invB);
        }
    }
}

// ============ host launcher ============
extern "C" void kernel_launch(void* const* d_in, const int* in_sizes, int n_in,
                              void* d_out, int out_size) {
    const float* x     = (const float*)d_in[0];
    const int*   rpi   = (const int*)d_in[1];
    const float* mask  = (const float*)d_in[2];
    const float* n1g   = (const float*)d_in[3];
    const float* n1b   = (const float*)d_in[4];
    const float* qkvw  = (const float*)d_in[5];
    const float* qkvb  = (const float*)d_in[6];
    const float* rpb   = (const float*)d_in[7];
    const float* projw = (const float*)d_in[8];
    const float* projb = (const float*)d_in[9];
    const float* n2g   = (const float*)d_in[10];
    const float* n2b   = (const float*)d_in[11];
    const float* fc1w  = (const float*)d_in[12];
    const float* fc1b  = (const float*)d_in[13];
    const float* fc2w  = (const float*)d_in[14];
    const float* fc2b  = (const float*)d_in[15];
    float* out = (float*)d_out;

    cudaFuncSetAttribute(attn_mma, cudaFuncAttributeMaxDynamicSharedMemorySize, ATT_SMEM);
    cudaFuncSetAttribute(tmmaA<0>, cudaFuncAttributeMaxDynamicSharedMemorySize, ARES_SMEM);
    cudaFuncSetAttribute(tmmaA<1>, cudaFuncAttributeMaxDynamicSharedMemorySize, ARES_SMEM);
    cudaFuncSetAttribute(tmmaA<2>, cudaFuncAttributeMaxDynamicSharedMemorySize, ARES_SMEM);
    cudaFuncSetAttribute(tmmaF, cudaFuncAttributeMaxDynamicSharedMemorySize, FC2_SMEM);

    prep_kernel<<<2560, 256>>>(qkvw, projw, fc1w, fc2w, rpi, rpb, x, n1g, n1b);

    tmmaA<0><<<512, 128, ARES_SMEM>>>(qkvb, nullptr, nullptr, 9);       // QKV -> q/k/v bf16
    attn_mma<<<1536, 256, ATT_SMEM>>>(mask);                            // attention -> g_aob
    tmmaA<1><<<512, 128, ARES_SMEM>>>(projb, x, nullptr, 3);            // proj + reverse + resid
    ln_kernel<<<592, 256>>>(n2g, n2b);                                  // LN2 (reads g_xr)
    tmmaA<2><<<512, 128, ARES_SMEM>>>(fc1b, nullptr, nullptr, 12);      // fc1 + GELU -> g_hb
    tmmaF<<<512, 256, FC2_SMEM>>>(fc2b, out);                           // fc2 + resid -> out
}